// round 10
// baseline (speedup 1.0000x reference)
#include <cuda_runtime.h>
#include <cstdint>

// ---------------------------------------------------------------------------
// onsets (B=64, T=8192, N=16, C=2) fp32.
//   onset[b,t] = any(onsets[b,t,n,0] > 0 over n)
//   out[b,t]   = t - (index of most recent onset <= t, else -1)   (fp32)
//
// Two kernels:
//   pass 1: 64 MiB -> 64 KiB bitmask, pure streaming (unchanged from R7).
//   pass 2: warp-autonomous: one warp per 256-frame chunk, no smem/barriers.
// ---------------------------------------------------------------------------

static constexpr int B = 64;
static constexpr int T = 8192;
static constexpr int WORDS_PER_B = T / 32;          // 256
static constexpr int TOTAL_WORDS = B * WORDS_PER_B; // 16384

// bit (t%32) of word (b*256 + t/32) = onset flag at (b,t)
__device__ uint32_t g_onset_mask[TOTAL_WORDS];

// ---------------------------------------------------------------------------
// Pass 1 (identical to R7's measured-fast version): one warp per 32 frames.
// Warp loads 4 KiB contiguous as 8 rounds of 512 B; 8 loads in flight per
// thread, then 8 ballots assemble the 32-bit mask word.
// ---------------------------------------------------------------------------
__global__ void __launch_bounds__(256)
onset_flags_kernel(const float4* __restrict__ in)
{
    const int warp = (blockIdx.x * 256 + threadIdx.x) >> 5;
    const int lane = threadIdx.x & 31;

    const float4* p = in + (size_t)warp * 256 + lane;

    float m[8];
    #pragma unroll
    for (int i = 0; i < 8; i++) {
        float4 v = __ldcs(p + i * 32);
        m[i] = fmaxf(v.x, v.z);                 // channel 0 = even floats
    }

    uint32_t bits = 0;
    #pragma unroll
    for (int i = 0; i < 8; i++) {
        unsigned bal = __ballot_sync(0xFFFFFFFFu, m[i] > 0.0f);
        #pragma unroll
        for (int j = 0; j < 4; j++)
            bits |= (((bal >> (8 * j)) & 0xFFu) ? 1u : 0u) << (i * 4 + j);
    }

    if (lane == 0)
        g_onset_mask[warp] = bits;
}

// ---------------------------------------------------------------------------
// Pass 2: one warp per 256-frame chunk (8 mask words). 2048 warps total.
// No shared memory, no block barriers — each warp:
//   (a) loads <=248 earlier words of its batch (8 predicated loads/lane,
//       stride 32) and max-reduces "last onset before chunk" via shuffles
//   (b) lanes 0..7 load the chunk's 8 words; 3-step shuffle exclusive scan
//   (c) each lane emits 8 frames as 2 fully-coalesced float4 stores
// ---------------------------------------------------------------------------
__global__ void __launch_bounds__(128)
onset_scan_kernel(float* __restrict__ out)
{
    const int gw   = (blockIdx.x * 128 + threadIdx.x) >> 5;  // global warp id
    const int lane = threadIdx.x & 31;
    const int b    = gw >> 5;                 // 32 chunks per batch
    const int c    = gw & 31;

    const uint32_t* __restrict__ mask = g_onset_mask + b * WORDS_PER_B;
    const int w0 = c * 8;                     // first word of chunk (0..248)

    // (a) prefix: last onset index over words [0, w0), else -1
    int pre = -1;
    #pragma unroll
    for (int r = 0; r < 8; r++) {
        const int idx = lane + r * 32;
        if (idx < w0) {
            uint32_t w = __ldcg(mask + idx);
            if (w) pre = max(pre, idx * 32 + 31 - __clz(w));
        }
    }
    #pragma unroll
    for (int off = 16; off; off >>= 1)
        pre = max(pre, __shfl_xor_sync(0xFFFFFFFFu, pre, off));

    // (b) own 8 words on lanes 0..7; exclusive max-scan
    uint32_t myw = (lane < 8) ? __ldcg(mask + w0 + lane) : 0u;
    int v = myw ? ((w0 + lane) * 32 + 31 - __clz(myw)) : -1;
    #pragma unroll
    for (int off = 1; off < 8; off <<= 1) {
        int u = __shfl_up_sync(0xFFFFFFFFu, v, off);
        if (lane >= off) v = max(v, u);
    }
    int up   = __shfl_up_sync(0xFFFFFFFFu, v, 1);
    int excl = (lane == 0) ? pre : max(pre, up);   // meaningful on lanes 0..7

    // (c) emit 64 float4 (256 frames), 2 coalesced rounds of 32 lanes
    float4* dst = reinterpret_cast<float4*>(out + (size_t)b * T + c * 256);
    #pragma unroll
    for (int q = 0; q < 2; q++) {
        const int f  = q * 32 + lane;          // float4 index within chunk
        const int wl = f >> 3;                 // word within chunk (0..7)
        const uint32_t word = __shfl_sync(0xFFFFFFFFu, myw, wl);
        const int ex        = __shfl_sync(0xFFFFFFFFu, excl, wl);
        const int tbase = (w0 + wl) * 32;      // frame base of that word
        const int j0    = (f & 7) * 4;         // starting bit

        float o[4];
        #pragma unroll
        for (int k = 0; k < 4; k++) {
            const int j = j0 + k;
            const uint32_t mk = word & (0xFFFFFFFFu >> (31 - j));
            const int last = mk ? (tbase + 31 - __clz(mk)) : ex;
            o[k] = (float)(tbase + j - last);
        }
        dst[f] = make_float4(o[0], o[1], o[2], o[3]);
    }
}

// ---------------------------------------------------------------------------
extern "C" void kernel_launch(void* const* d_in, const int* in_sizes, int n_in,
                              void* d_out, int out_size)
{
    const float4* in = (const float4*)d_in[0];
    float* out = (float*)d_out;

    onset_flags_kernel<<<(B * T / 32) / 8, 256>>>(in);  // 2048 CTAs
    onset_scan_kernel<<<(B * 32) / 4, 128>>>(out);      // 512 CTAs, 2048 warps
}

// round 11
// speedup vs baseline: 1.1546x; 1.1546x over previous
#include <cuda_runtime.h>
#include <cstdint>

// ---------------------------------------------------------------------------
// onsets (B=64, T=8192, N=16, C=2) fp32.
//   onset[b,t] = any(onsets[b,t,n,0] > 0 over n)
//   out[b,t]   = t - (index of most recent onset <= t, else -1)   (fp32)
//
// Three shallow kernels:
//   1. flags : 64 MiB -> 16384-word bitmask (LTS-cap streaming, ~5.9us)
//   2. prefix: per-batch exclusive max-scan over 256 words -> g_excl
//   3. emit  : one thread per float4, pure gather-compute-store
// ---------------------------------------------------------------------------

static constexpr int B = 64;
static constexpr int T = 8192;
static constexpr int WORDS_PER_B = T / 32;          // 256
static constexpr int TOTAL_WORDS = B * WORDS_PER_B; // 16384

// bit (t%32) of word (b*256 + t/32) = onset flag at (b,t)
__device__ uint32_t g_onset_mask[TOTAL_WORDS];
// g_excl[w] = last onset frame index (within batch) in words < w, else -1
__device__ int      g_excl[TOTAL_WORDS];

// ---------------------------------------------------------------------------
// Kernel 1: one warp per 32 frames; warp streams 4 KiB contiguous as 8
// rounds of 512 B (8 loads in flight/thread), 8 ballots -> one mask word.
// ---------------------------------------------------------------------------
__global__ void __launch_bounds__(256)
onset_flags_kernel(const float4* __restrict__ in)
{
    const int warp = (blockIdx.x * 256 + threadIdx.x) >> 5;
    const int lane = threadIdx.x & 31;

    const float4* p = in + (size_t)warp * 256 + lane;

    float m[8];
    #pragma unroll
    for (int i = 0; i < 8; i++) {
        float4 v = __ldcs(p + i * 32);
        m[i] = fmaxf(v.x, v.z);                 // channel 0 = even floats
    }

    uint32_t bits = 0;
    #pragma unroll
    for (int i = 0; i < 8; i++) {
        unsigned bal = __ballot_sync(0xFFFFFFFFu, m[i] > 0.0f);
        #pragma unroll
        for (int j = 0; j < 4; j++)
            bits |= (((bal >> (8 * j)) & 0xFFu) ? 1u : 0u) << (i * 4 + j);
    }

    if (lane == 0)
        g_onset_mask[warp] = bits;
}

// ---------------------------------------------------------------------------
// Kernel 2: 64 CTAs (one per batch), 256 threads (one per word).
// Block-wide EXCLUSIVE max-scan of "last onset index in word", seeded -1.
// ---------------------------------------------------------------------------
__global__ void __launch_bounds__(256)
onset_prefix_kernel()
{
    const int b    = blockIdx.x;
    const int tid  = threadIdx.x;
    const int lane = tid & 31;
    const int wid  = tid >> 5;

    const uint32_t w = g_onset_mask[b * WORDS_PER_B + tid];
    int v = w ? (tid * 32 + 31 - __clz(w)) : -1;   // frame index within batch

    // warp-inclusive max scan
    #pragma unroll
    for (int off = 1; off < 32; off <<= 1) {
        int u = __shfl_up_sync(0xFFFFFFFFu, v, off);
        if (lane >= off) v = max(v, u);
    }

    __shared__ int s_warp[8];
    if (lane == 31) s_warp[wid] = v;
    __syncthreads();

    int woff = -1;                                  // exclusive across warps
    #pragma unroll
    for (int i = 0; i < 8; i++)
        if (i < wid) woff = max(woff, s_warp[i]);

    int up = __shfl_up_sync(0xFFFFFFFFu, v, 1);
    int excl = (lane == 0) ? woff : max(woff, up);

    g_excl[b * WORDS_PER_B + tid] = excl;
}

// ---------------------------------------------------------------------------
// Kernel 3: one thread per output float4 (131072 threads). No barriers, no
// shuffles: read word + excl (L2-hot, 8-way broadcast), compute 4, STG.128.
// ---------------------------------------------------------------------------
__global__ void __launch_bounds__(256)
onset_emit_kernel(float4* __restrict__ out)
{
    const int gid = blockIdx.x * 256 + threadIdx.x;   // float4 index
    const int wi  = gid >> 3;                         // global word index
    const int j0  = (gid & 7) * 4;                    // starting bit in word

    const uint32_t word = __ldg(&g_onset_mask[wi]);
    const int      excl = __ldg(&g_excl[wi]);
    const int tbase = (wi & (WORDS_PER_B - 1)) * 32;  // word's frame base

    float o[4];
    #pragma unroll
    for (int k = 0; k < 4; k++) {
        const int j = j0 + k;
        const uint32_t mk = word & (0xFFFFFFFFu >> (31 - j)); // bits <= j
        const int last = mk ? (tbase + 31 - __clz(mk)) : excl;
        o[k] = (float)(tbase + j - last);
    }
    out[gid] = make_float4(o[0], o[1], o[2], o[3]);
}

// ---------------------------------------------------------------------------
extern "C" void kernel_launch(void* const* d_in, const int* in_sizes, int n_in,
                              void* d_out, int out_size)
{
    const float4* in = (const float4*)d_in[0];
    float4* out = (float4*)d_out;

    onset_flags_kernel <<<(B * T / 32) / 8, 256>>>(in);   // 2048 CTAs
    onset_prefix_kernel<<<B, 256>>>();                    // 64 CTAs
    onset_emit_kernel  <<<(B * T / 4) / 256, 256>>>(out); // 512 CTAs
}